// round 7
// baseline (speedup 1.0000x reference)
#include <cuda_runtime.h>
#include <cuda_bf16.h>
#include <cstdint>
#include <math.h>

#define BB 64
#define TT 512
#define EE 256
#define HH 768
#define G4 3072
#define VV 5000

// ---------------- device scratch (no allocation allowed) ----------------
__device__ float g_proj[(size_t)VV * G4];        // embed@W_ih^T + b_ih + b_hh (61.4 MB)
__device__ float g_W2hi[(size_t)G4 * HH];        // gathered W_hh, tf32 hi part
__device__ float g_W2lo[(size_t)G4 * HH];        // gathered W_hh, tf32 lo residual
__device__ float g_hall[(size_t)TT * BB * HH];   // h states, [T][B][H] fp32 (100 MB)
__device__ float g_c[BB * HH];                   // cell state [B][H]

__device__ __forceinline__ float to_tf32(float x){
    uint32_t u; asm("cvt.rna.tf32.f32 %0, %1;" : "=r"(u) : "f"(x));
    return __uint_as_float(u);
}
__device__ __forceinline__ uint32_t fu(float x){ return __float_as_uint(x); }

__device__ __forceinline__ void mma_tf32(float* c, const uint32_t* a, const uint32_t* b){
    asm volatile("mma.sync.aligned.m16n8k8.row.col.f32.tf32.tf32.f32 "
        "{%0,%1,%2,%3}, {%4,%5,%6,%7}, {%8,%9}, {%0,%1,%2,%3};"
        : "+f"(c[0]), "+f"(c[1]), "+f"(c[2]), "+f"(c[3])
        : "r"(a[0]), "r"(a[1]), "r"(a[2]), "r"(a[3]), "r"(b[0]), "r"(b[1]));
}

// ---------------- prep: zero c, gather + split W_hh ----------------
// Step-CTA `cta` owns hidden units [cta*8, cta*8+8). Local row r in [0,32):
// unit u = cta*8 + (r>>2), gate = r&3 -> W_hh global row = gate*HH + u.
__global__ void k_prep(const float* __restrict__ Whh){
    int i = blockIdx.x * blockDim.x + threadIdx.x;
    if (i < BB * HH) g_c[i] = 0.f;
    if (i < G4 * HH){
        int g = i / HH, k = i - g * HH;
        int cta = g >> 5, r = g & 31;
        int grow = (r & 3) * HH + (cta << 3) + (r >> 2);
        float w = Whh[(size_t)grow * HH + k];
        float hi = to_tf32(w);
        g_W2hi[i] = hi;
        g_W2lo[i] = to_tf32(w - hi);
    }
}

// ---------------- generic tf32 GEMM: C = A[M,K] @ B[N,K]^T + bias ----------------
// 128x128 tile, kt=32, 256 threads, 8 warps as 4m x 2n (warp region 32m x 64n).
// Tile fill: 128 rows x 32 cols = 1024 float4 => 4 float4 per thread.
// PERM: output row permutation m=(t*64+b) -> orow=(b*512+t)  (for the FC).
template<bool PERM>
__global__ __launch_bounds__(256) void k_gemm(
    const float* __restrict__ A, const float* __restrict__ Bm, float* __restrict__ C,
    int M, int N, int K, const float* __restrict__ bias1, const float* __restrict__ bias2)
{
    __shared__ float As[128][36];
    __shared__ float Bs[128][36];
    const int tid = threadIdx.x;
    const int w = tid >> 5, lane = tid & 31;
    const int lr = lane >> 2, lc = lane & 3;
    const int m0 = blockIdx.y * 128, n0 = blockIdx.x * 128;
    const int wm = (w >> 1) * 32, wn = (w & 1) * 64;

    float acc[2][8][4];
    #pragma unroll
    for (int i = 0; i < 2; i++)
        #pragma unroll
        for (int j = 0; j < 8; j++)
            #pragma unroll
            for (int q = 0; q < 4; q++) acc[i][j][q] = 0.f;

    float4 pa[4], pb[4];
    #pragma unroll
    for (int i = 0; i < 4; i++){
        int f = tid + i * 256; int r = f >> 3, cf = (f & 7) * 4;
        pa[i] = make_float4(0.f,0.f,0.f,0.f);
        if (m0 + r < M) pa[i] = *(const float4*)(A + (size_t)(m0 + r) * K + cf);
        pb[i] = make_float4(0.f,0.f,0.f,0.f);
        if (n0 + r < N) pb[i] = *(const float4*)(Bm + (size_t)(n0 + r) * K + cf);
    }

    for (int k0 = 0; k0 < K; k0 += 32){
        #pragma unroll
        for (int i = 0; i < 4; i++){
            int f = tid + i * 256; int r = f >> 3, cf = (f & 7) * 4;
            float4 ta = pa[i], tb = pb[i];
            As[r][cf+0] = to_tf32(ta.x); As[r][cf+1] = to_tf32(ta.y);
            As[r][cf+2] = to_tf32(ta.z); As[r][cf+3] = to_tf32(ta.w);
            Bs[r][cf+0] = to_tf32(tb.x); Bs[r][cf+1] = to_tf32(tb.y);
            Bs[r][cf+2] = to_tf32(tb.z); Bs[r][cf+3] = to_tf32(tb.w);
        }
        __syncthreads();
        int k1 = k0 + 32;
        if (k1 < K){
            #pragma unroll
            for (int i = 0; i < 4; i++){
                int f = tid + i * 256; int r = f >> 3, cf = (f & 7) * 4;
                pa[i] = make_float4(0.f,0.f,0.f,0.f);
                if (m0 + r < M) pa[i] = *(const float4*)(A + (size_t)(m0 + r) * K + k1 + cf);
                pb[i] = make_float4(0.f,0.f,0.f,0.f);
                if (n0 + r < N) pb[i] = *(const float4*)(Bm + (size_t)(n0 + r) * K + k1 + cf);
            }
        }
        #pragma unroll
        for (int kk = 0; kk < 32; kk += 8){
            uint32_t af[2][4], bf[8][2];
            #pragma unroll
            for (int mt = 0; mt < 2; mt++){
                int rb = wm + mt * 16;
                af[mt][0] = fu(As[rb + lr][kk + lc]);
                af[mt][1] = fu(As[rb + 8 + lr][kk + lc]);
                af[mt][2] = fu(As[rb + lr][kk + lc + 4]);
                af[mt][3] = fu(As[rb + 8 + lr][kk + lc + 4]);
            }
            #pragma unroll
            for (int nt = 0; nt < 8; nt++){
                int cb = wn + nt * 8;
                bf[nt][0] = fu(Bs[cb + lr][kk + lc]);
                bf[nt][1] = fu(Bs[cb + lr][kk + lc + 4]);
            }
            #pragma unroll
            for (int mt = 0; mt < 2; mt++)
                #pragma unroll
                for (int nt = 0; nt < 8; nt++)
                    mma_tf32(acc[mt][nt], af[mt], bf[nt]);
        }
        __syncthreads();
    }

    #pragma unroll
    for (int mt = 0; mt < 2; mt++)
        #pragma unroll
        for (int nt = 0; nt < 8; nt++){
            #pragma unroll
            for (int q = 0; q < 4; q++){
                int row = m0 + wm + mt * 16 + lr + (q >> 1) * 8;
                int col = n0 + wn + nt * 8 + lc * 2 + (q & 1);
                if (row < M && col < N){
                    float v = acc[mt][nt][q];
                    if (bias1) v += bias1[col];
                    if (bias2) v += bias2[col];
                    int orow = row;
                    if (PERM){ int t = row >> 6, b = row & 63; orow = b * TT + t; }
                    C[(size_t)orow * N + col] = v;
                }
            }
        }
}

// ---------------- one LSTM timestep (tf32x3, effectively fp32-exact) ----------------
// 96 CTAs; CTA owns 8 hidden units -> gate tile [64 batch x 32 rows], K=768.
// 256 threads, 8 warps as 4m x 2n (warp region 16m x 16n).
__global__ __launch_bounds__(256) void k_step(const int* __restrict__ x, int t)
{
    __shared__ float Ah[64][36];
    __shared__ float Al[64][36];
    __shared__ float Bh[32][36];
    __shared__ float Bl[32][36];
    __shared__ float gs[64][33];
    const int tid = threadIdx.x;
    const int w = tid >> 5, lane = tid & 31;
    const int lr = lane >> 2, lc = lane & 3;
    const int wm = (w >> 1) * 16, wn = (w & 1) * 16;
    const int cta = blockIdx.x;
    const float* __restrict__ BHp = g_W2hi + (size_t)cta * 32 * HH;
    const float* __restrict__ BLp = g_W2lo + (size_t)cta * 32 * HH;
    const float* hp = (t == 0) ? (const float*)0 : (g_hall + (size_t)(t - 1) * BB * HH);

    float acc[2][4];
    #pragma unroll
    for (int j = 0; j < 2; j++)
        #pragma unroll
        for (int q = 0; q < 4; q++) acc[j][q] = 0.f;

    // thread load map: A tile 64x32 = 512 float4 -> 2/thread; B tiles 32x32 = 256 float4 -> 1/thread each
    float4 pa[2], pbh, pbl;
    const int rA0 = tid >> 3, cA = (tid & 7) * 4;
    const int rA1 = (tid + 256) >> 3;
    const int rB = tid >> 3;
    pa[0] = make_float4(0.f,0.f,0.f,0.f);
    pa[1] = make_float4(0.f,0.f,0.f,0.f);
    if (hp){
        pa[0] = *(const float4*)(hp + (size_t)rA0 * HH + cA);
        pa[1] = *(const float4*)(hp + (size_t)rA1 * HH + cA);
    }
    pbh = *(const float4*)(BHp + (size_t)rB * HH + cA);
    pbl = *(const float4*)(BLp + (size_t)rB * HH + cA);

    for (int k0 = 0; k0 < HH; k0 += 32){
        // split A into tf32 hi/lo; B already split
        {
            float4 v = pa[0];
            float h0 = to_tf32(v.x), h1 = to_tf32(v.y), h2 = to_tf32(v.z), h3 = to_tf32(v.w);
            Ah[rA0][cA+0]=h0; Ah[rA0][cA+1]=h1; Ah[rA0][cA+2]=h2; Ah[rA0][cA+3]=h3;
            Al[rA0][cA+0]=to_tf32(v.x-h0); Al[rA0][cA+1]=to_tf32(v.y-h1);
            Al[rA0][cA+2]=to_tf32(v.z-h2); Al[rA0][cA+3]=to_tf32(v.w-h3);
            v = pa[1];
            h0 = to_tf32(v.x); h1 = to_tf32(v.y); h2 = to_tf32(v.z); h3 = to_tf32(v.w);
            Ah[rA1][cA+0]=h0; Ah[rA1][cA+1]=h1; Ah[rA1][cA+2]=h2; Ah[rA1][cA+3]=h3;
            Al[rA1][cA+0]=to_tf32(v.x-h0); Al[rA1][cA+1]=to_tf32(v.y-h1);
            Al[rA1][cA+2]=to_tf32(v.z-h2); Al[rA1][cA+3]=to_tf32(v.w-h3);
            *(float4*)&Bh[rB][cA] = pbh;
            *(float4*)&Bl[rB][cA] = pbl;
        }
        __syncthreads();
        int k1 = k0 + 32;
        if (k1 < HH){
            if (hp){
                pa[0] = *(const float4*)(hp + (size_t)rA0 * HH + k1 + cA);
                pa[1] = *(const float4*)(hp + (size_t)rA1 * HH + k1 + cA);
            }
            pbh = *(const float4*)(BHp + (size_t)rB * HH + k1 + cA);
            pbl = *(const float4*)(BLp + (size_t)rB * HH + k1 + cA);
        }
        #pragma unroll
        for (int kk = 0; kk < 32; kk += 8){
            uint32_t ah[4], al[4], bh[2][2], bl[2][2];
            ah[0] = fu(Ah[wm + lr][kk + lc]);
            ah[1] = fu(Ah[wm + 8 + lr][kk + lc]);
            ah[2] = fu(Ah[wm + lr][kk + lc + 4]);
            ah[3] = fu(Ah[wm + 8 + lr][kk + lc + 4]);
            al[0] = fu(Al[wm + lr][kk + lc]);
            al[1] = fu(Al[wm + 8 + lr][kk + lc]);
            al[2] = fu(Al[wm + lr][kk + lc + 4]);
            al[3] = fu(Al[wm + 8 + lr][kk + lc + 4]);
            #pragma unroll
            for (int nt = 0; nt < 2; nt++){
                int cb = wn + nt * 8;
                bh[nt][0] = fu(Bh[cb + lr][kk + lc]);
                bh[nt][1] = fu(Bh[cb + lr][kk + lc + 4]);
                bl[nt][0] = fu(Bl[cb + lr][kk + lc]);
                bl[nt][1] = fu(Bl[cb + lr][kk + lc + 4]);
            }
            #pragma unroll
            for (int nt = 0; nt < 2; nt++){
                mma_tf32(acc[nt], ah, bh[nt]);
                mma_tf32(acc[nt], ah, bl[nt]);
                mma_tf32(acc[nt], al, bh[nt]);
            }
        }
        __syncthreads();
    }

    // write gate tile to smem
    #pragma unroll
    for (int nt = 0; nt < 2; nt++){
        #pragma unroll
        for (int q = 0; q < 4; q++){
            int row = wm + lr + (q >> 1) * 8;
            int col = wn + nt * 8 + lc * 2 + (q & 1);
            gs[row][col] = acc[nt][q];
        }
    }
    __syncthreads();

    // pointwise LSTM for (b, u): rows 4u..4u+3 = gates i,f,g,o of unit cta*8+u
    #pragma unroll
    for (int j = 0; j < 2; j++){
        int idx = tid + j * 256;           // [0,512)
        int b = idx & 63, u = idx >> 6;    // u in [0,8)
        int ug = (cta << 3) + u;           // global hidden unit
        int xv = x[b * TT + t];
        const float* pr = g_proj + (size_t)xv * G4;
        float gi = gs[b][4*u+0] + pr[0*HH + ug];
        float gf = gs[b][4*u+1] + pr[1*HH + ug];
        float gg = gs[b][4*u+2] + pr[2*HH + ug];
        float go = gs[b][4*u+3] + pr[3*HH + ug];
        float si = 1.f / (1.f + expf(-gi));
        float sf = 1.f / (1.f + expf(-gf));
        float so = 1.f / (1.f + expf(-go));
        float cold = g_c[b * HH + ug];
        float cnew = sf * cold + si * tanhf(gg);
        float hnew = so * tanhf(cnew);
        g_c[b * HH + ug] = cnew;
        g_hall[(size_t)t * BB * HH + (size_t)b * HH + ug] = hnew;
    }
}

// ---------------- host launch ----------------
extern "C" void kernel_launch(void* const* d_in, const int* in_sizes, int n_in,
                              void* d_out, int out_size)
{
    const int* x = 0;
    const float *embed = 0, *W_ih = 0, *W_hh = 0, *b_ih = 0, *b_hh = 0, *fc_w = 0, *fc_b = 0;
    for (int i = 0; i < n_in; i++){
        switch (in_sizes[i]){
            case BB*TT:      x     = (const int*)  d_in[i]; break;
            case VV*EE:      embed = (const float*)d_in[i]; break;
            case G4*EE:      W_ih  = (const float*)d_in[i]; break;
            case G4*HH:      W_hh  = (const float*)d_in[i]; break;
            case G4:         if (!b_ih) b_ih = (const float*)d_in[i];
                             else        b_hh = (const float*)d_in[i]; break;
            case VV*HH:      fc_w  = (const float*)d_in[i]; break;
            case VV:         fc_b  = (const float*)d_in[i]; break;
            default: break;  // truncate_length (size 1) — forward-identity, ignored
        }
    }
    float* out = (float*)d_out;

    float *p_proj = 0, *p_hall = 0;
    cudaGetSymbolAddress((void**)&p_proj, g_proj);
    cudaGetSymbolAddress((void**)&p_hall, g_hall);

    // 1) prep: zero c, gather + tf32-split W_hh
    {
        int n = G4 * HH;
        k_prep<<<(n + 255) / 256, 256>>>(W_hh);
    }
    // 2) proj[V,4H] = embed @ W_ih^T + b_ih + b_hh
    {
        dim3 grid(G4 / 128, (VV + 127) / 128);
        k_gemm<false><<<grid, 256>>>(embed, W_ih, p_proj, VV, G4, EE, b_ih, b_hh);
    }
    // 3) recurrence: 512 sequential steps
    for (int t = 0; t < TT; t++)
        k_step<<<96, 256>>>(x, t);
    // 4) out[B,T,V] = hall @ fc_w^T + fc_b  (with [T,B]->[B,T] row permutation)
    {
        dim3 grid((VV + 127) / 128, (BB * TT) / 128);
        k_gemm<true><<<grid, 256>>>(p_hall, fc_w, out, BB * TT, VV, HH, fc_b, (const float*)0);
    }
}

// round 8
// speedup vs baseline: 1.3115x; 1.3115x over previous
#include <cuda_runtime.h>
#include <cuda_bf16.h>
#include <cstdint>
#include <math.h>

#define BB 64
#define TT 512
#define EE 256
#define HH 768
#define G4 3072
#define VV 5000

#define NCTA 128          // persistent CTAs, 6 units each
#define UPC  6            // units per CTA
#define ROWS 24           // gate rows per CTA (4 gates x 6 units)
#define NKK  96           // K=768 / 8
#define WFRAG_F4_PER_CTA (NKK*3*32)        // 9216 float4
#define HFRAG_F 49152                      // 64*768 floats per slot/part

// ---------------- device scratch ----------------
__device__ float g_proj[(size_t)VV * G4];            // embed@W_ih^T + biases
__device__ float g_wfrag[(size_t)NCTA * WFRAG_F4_PER_CTA * 4]; // W_hh, B-fragment order, hi/lo interleaved
__device__ float g_hall[(size_t)TT * BB * HH];       // h states row-major [t][b][H] (FC input)
__device__ float g_fhi[2][HFRAG_F];                  // h tf32-hi, A-fragment order, double-buffered
__device__ float g_flo[2][HFRAG_F];                  // h tf32-lo residual
__device__ unsigned g_cnt = 0;                       // barrier arrive count (self-resetting)
__device__ unsigned g_gen = 0;                       // barrier generation (monotonic)

__device__ __forceinline__ float to_tf32(float x){
    uint32_t u; asm("cvt.rna.tf32.f32 %0, %1;" : "=r"(u) : "f"(x));
    return __uint_as_float(u);
}
__device__ __forceinline__ uint32_t fu(float x){ return __float_as_uint(x); }

__device__ __forceinline__ void mma_tf32(float* c, const uint32_t* a, const uint32_t* b){
    asm volatile("mma.sync.aligned.m16n8k8.row.col.f32.tf32.tf32.f32 "
        "{%0,%1,%2,%3}, {%4,%5,%6,%7}, {%8,%9}, {%0,%1,%2,%3};"
        : "+f"(c[0]), "+f"(c[1]), "+f"(c[2]), "+f"(c[3])
        : "r"(a[0]), "r"(a[1]), "r"(a[2]), "r"(a[3]), "r"(b[0]), "r"(b[1]));
}

// ---------------- prep: build fragment-ordered W_hh (hi/lo), zero hfrag slot 1 ----------------
// B-fragment (m16n8k8 col-major): lane holds b0=(k=lc,n=lr), b1=(k=lc+4,n=lr), lr=lane>>2, lc=lane&3.
// CTA row n_local in [0,24): unit u=n_local>>2, gate=n_local&3 -> W_hh row = gate*HH + cta*6 + u.
// float4 at ((cta*96 + kk8)*3 + nt)*32 + lane = {hi(k), hi(k+4), lo(k), lo(k+4)}.
__global__ void k_prep(const float* __restrict__ Whh){
    int i = blockIdx.x * blockDim.x + threadIdx.x;
    if (i < HFRAG_F){ g_fhi[1][i] = 0.f; g_flo[1][i] = 0.f; }
    if (i < NCTA * WFRAG_F4_PER_CTA){
        int cta = i / WFRAG_F4_PER_CTA;
        int j   = i % WFRAG_F4_PER_CTA;
        int kk8 = j / 96;
        int j2  = j % 96;
        int nt  = j2 >> 5;
        int lane= j2 & 31;
        int n_local = nt*8 + (lane >> 2);
        int k0 = kk8*8 + (lane & 3);
        int u = n_local >> 2, gate = n_local & 3;
        int grow = gate*HH + cta*UPC + u;
        float w0 = Whh[(size_t)grow * HH + k0];
        float w1 = Whh[(size_t)grow * HH + k0 + 4];
        float h0 = to_tf32(w0), h1 = to_tf32(w1);
        float4 v = make_float4(h0, h1, to_tf32(w0 - h0), to_tf32(w1 - h1));
        ((float4*)g_wfrag)[i] = v;
    }
}

// ---------------- generic tf32 GEMM: C = A[M,K] @ B[N,K]^T + bias ----------------
// 128x128 tile, kt=32, 256 threads, 8 warps 4m x 2n. PERM remaps (t*64+b) -> (b*512+t).
template<bool PERM>
__global__ __launch_bounds__(256) void k_gemm(
    const float* __restrict__ A, const float* __restrict__ Bm, float* __restrict__ C,
    int M, int N, int K, const float* __restrict__ bias1, const float* __restrict__ bias2)
{
    __shared__ float As[128][36];
    __shared__ float Bs[128][36];
    const int tid = threadIdx.x;
    const int w = tid >> 5, lane = tid & 31;
    const int lr = lane >> 2, lc = lane & 3;
    const int m0 = blockIdx.y * 128, n0 = blockIdx.x * 128;
    const int wm = (w >> 1) * 32, wn = (w & 1) * 64;

    float acc[2][8][4];
    #pragma unroll
    for (int i = 0; i < 2; i++)
        #pragma unroll
        for (int j = 0; j < 8; j++)
            #pragma unroll
            for (int q = 0; q < 4; q++) acc[i][j][q] = 0.f;

    float4 pa[4], pb[4];
    #pragma unroll
    for (int i = 0; i < 4; i++){
        int f = tid + i * 256; int r = f >> 3, cf = (f & 7) * 4;
        pa[i] = make_float4(0.f,0.f,0.f,0.f);
        if (m0 + r < M) pa[i] = *(const float4*)(A + (size_t)(m0 + r) * K + cf);
        pb[i] = make_float4(0.f,0.f,0.f,0.f);
        if (n0 + r < N) pb[i] = *(const float4*)(Bm + (size_t)(n0 + r) * K + cf);
    }

    for (int k0 = 0; k0 < K; k0 += 32){
        #pragma unroll
        for (int i = 0; i < 4; i++){
            int f = tid + i * 256; int r = f >> 3, cf = (f & 7) * 4;
            float4 ta = pa[i], tb = pb[i];
            As[r][cf+0] = to_tf32(ta.x); As[r][cf+1] = to_tf32(ta.y);
            As[r][cf+2] = to_tf32(ta.z); As[r][cf+3] = to_tf32(ta.w);
            Bs[r][cf+0] = to_tf32(tb.x); Bs[r][cf+1] = to_tf32(tb.y);
            Bs[r][cf+2] = to_tf32(tb.z); Bs[r][cf+3] = to_tf32(tb.w);
        }
        __syncthreads();
        int k1 = k0 + 32;
        if (k1 < K){
            #pragma unroll
            for (int i = 0; i < 4; i++){
                int f = tid + i * 256; int r = f >> 3, cf = (f & 7) * 4;
                pa[i] = make_float4(0.f,0.f,0.f,0.f);
                if (m0 + r < M) pa[i] = *(const float4*)(A + (size_t)(m0 + r) * K + k1 + cf);
                pb[i] = make_float4(0.f,0.f,0.f,0.f);
                if (n0 + r < N) pb[i] = *(const float4*)(Bm + (size_t)(n0 + r) * K + k1 + cf);
            }
        }
        #pragma unroll
        for (int kk = 0; kk < 32; kk += 8){
            uint32_t af[2][4], bf[8][2];
            #pragma unroll
            for (int mt = 0; mt < 2; mt++){
                int rb = wm + mt * 16;
                af[mt][0] = fu(As[rb + lr][kk + lc]);
                af[mt][1] = fu(As[rb + 8 + lr][kk + lc]);
                af[mt][2] = fu(As[rb + lr][kk + lc + 4]);
                af[mt][3] = fu(As[rb + 8 + lr][kk + lc + 4]);
            }
            #pragma unroll
            for (int nt = 0; nt < 8; nt++){
                int cb = wn + nt * 8;
                bf[nt][0] = fu(Bs[cb + lr][kk + lc]);
                bf[nt][1] = fu(Bs[cb + lr][kk + lc + 4]);
            }
            #pragma unroll
            for (int mt = 0; mt < 2; mt++)
                #pragma unroll
                for (int nt = 0; nt < 8; nt++)
                    mma_tf32(acc[mt][nt], af[mt], bf[nt]);
        }
        __syncthreads();
    }

    #pragma unroll
    for (int mt = 0; mt < 2; mt++)
        #pragma unroll
        for (int nt = 0; nt < 8; nt++){
            #pragma unroll
            for (int q = 0; q < 4; q++){
                int row = m0 + wm + mt * 16 + lr + (q >> 1) * 8;
                int col = n0 + wn + nt * 8 + lc * 2 + (q & 1);
                if (row < M && col < N){
                    float v = acc[mt][nt][q];
                    if (bias1) v += bias1[col];
                    if (bias2) v += bias2[col];
                    int orow = row;
                    if (PERM){ int t = row >> 6, b = row & 63; orow = b * TT + t; }
                    C[(size_t)orow * N + col] = v;
                }
            }
        }
}

// ---------------- persistent LSTM recurrence ----------------
// 128 CTAs x 128 threads. CTA owns units [cta*6, cta*6+6). Warp w = m16 rows b in [w*16, w*16+16),
// all 24 gate columns (3 n8 tiles). tf32x3: acc = Ah*Bh + Ah*Bl + Al*Bh (3 independent acc sets).
__global__ __launch_bounds__(128, 1) void k_persist(const int* __restrict__ x)
{
    extern __shared__ float sm[];
    float4* Bsm = (float4*)sm;                 // 9216 float4 = 147456 B
    float*  gs  = sm + 4*WFRAG_F4_PER_CTA;     // 64 x 25 floats
    const int tid  = threadIdx.x;
    const int w    = tid >> 5, lane = tid & 31;
    const int lr   = lane >> 2, lc2 = (lane & 3) * 2;
    const int cta  = blockIdx.x;

    // persistent weight slice -> smem (fragment order, straight copy)
    {
        const float4* wsrc = ((const float4*)g_wfrag) + (size_t)cta * WFRAG_F4_PER_CTA;
        for (int i = tid; i < WFRAG_F4_PER_CTA; i += 128) Bsm[i] = wsrc[i];
    }

    // epilogue work items: 3 per thread -> (b, u)
    int eb[3], eu[3]; float creg[3];
    const int* xp[3];
    #pragma unroll
    for (int j = 0; j < 3; j++){
        int idx = tid + j * 128;
        eb[j] = idx & 63; eu[j] = idx >> 6;
        creg[j] = 0.f;
        xp[j] = x + eb[j] * TT;
    }
    __syncthreads();

    unsigned genbase = 0;
    if (tid == 0)
        asm volatile("ld.volatile.global.u32 %0, [%1];" : "=r"(genbase) : "l"(&g_gen));

    for (int t = 0; t < TT; t++){
        // prefetch proj gate biases + token (consumed in epilogue, hidden behind GEMM)
        float pv[3][4];
        #pragma unroll
        for (int j = 0; j < 3; j++){
            int xv = __ldg(xp[j] + t);
            const float* pr = g_proj + (size_t)xv * G4 + (cta * UPC + eu[j]);
            #pragma unroll
            for (int g = 0; g < 4; g++) pv[j][g] = __ldg(pr + g * HH);
        }

        const float4* Ahi = (const float4*)g_fhi[(t + 1) & 1];  // slot (t-1)&1; t=0 -> zeroed slot 1
        const float4* Alo = (const float4*)g_flo[(t + 1) & 1];

        float accHH[3][4], accHL[3][4], accLH[3][4];
        #pragma unroll
        for (int n = 0; n < 3; n++)
            #pragma unroll
            for (int q = 0; q < 4; q++){ accHH[n][q] = 0.f; accHL[n][q] = 0.f; accLH[n][q] = 0.f; }

        // 8-deep A-fragment prefetch ring (covers L2 latency)
        float4 ahb[8], alb[8];
        #pragma unroll
        for (int j = 0; j < 8; j++){
            int off = (j * 4 + w) * 32 + lane;
            ahb[j] = __ldg(Ahi + off);
            alb[j] = __ldg(Alo + off);
        }
        // B prefetch (one kk8 ahead)
        float4 bcur[3], bnxt[3];
        #pragma unroll
        for (int nt = 0; nt < 3; nt++) bcur[nt] = Bsm[nt * 32 + lane];

        for (int c = 0; c < 12; c++){
            #pragma unroll
            for (int j = 0; j < 8; j++){
                int kk8 = c * 8 + j;
                float4 a4 = ahb[j], l4 = alb[j];
                int kn = kk8 + 8;
                if (kn < NKK){
                    int off = (kn * 4 + w) * 32 + lane;
                    ahb[j] = __ldg(Ahi + off);
                    alb[j] = __ldg(Alo + off);
                }
                if (kk8 + 1 < NKK){
                    #pragma unroll
                    for (int nt = 0; nt < 3; nt++)
                        bnxt[nt] = Bsm[((kk8 + 1) * 3 + nt) * 32 + lane];
                }
                uint32_t ah[4] = {fu(a4.x), fu(a4.y), fu(a4.z), fu(a4.w)};
                uint32_t al[4] = {fu(l4.x), fu(l4.y), fu(l4.z), fu(l4.w)};
                #pragma unroll
                for (int nt = 0; nt < 3; nt++){
                    uint32_t bh[2] = {fu(bcur[nt].x), fu(bcur[nt].y)};
                    uint32_t bl[2] = {fu(bcur[nt].z), fu(bcur[nt].w)};
                    mma_tf32(accHH[nt], ah, bh);
                    mma_tf32(accHL[nt], ah, bl);
                    mma_tf32(accLH[nt], al, bh);
                }
                #pragma unroll
                for (int nt = 0; nt < 3; nt++) bcur[nt] = bnxt[nt];
            }
        }

        // gate tile -> smem
        #pragma unroll
        for (int nt = 0; nt < 3; nt++){
            #pragma unroll
            for (int q = 0; q < 4; q++){
                int row = w * 16 + lr + (q >> 1) * 8;
                int col = nt * 8 + lc2 + (q & 1);
                gs[row * 25 + col] = accHH[nt][q] + accHL[nt][q] + accLH[nt][q];
            }
        }
        __syncthreads();

        // pointwise LSTM + h scatter (row-major for FC, fragment-order hi/lo for next step)
        float* hdst_hi = g_fhi[t & 1];
        float* hdst_lo = g_flo[t & 1];
        float* hall_t  = g_hall + (size_t)t * (BB * HH);
        #pragma unroll
        for (int j = 0; j < 3; j++){
            int b = eb[j], u = eu[j], ug = cta * UPC + u;
            float gi = gs[b * 25 + 4*u + 0] + pv[j][0];
            float gf = gs[b * 25 + 4*u + 1] + pv[j][1];
            float gg = gs[b * 25 + 4*u + 2] + pv[j][2];
            float go = gs[b * 25 + 4*u + 3] + pv[j][3];
            float si = 1.f / (1.f + expf(-gi));
            float sf = 1.f / (1.f + expf(-gf));
            float so = 1.f / (1.f + expf(-go));
            float cnew = sf * creg[j] + si * tanhf(gg);
            float hnew = so * tanhf(cnew);
            creg[j] = cnew;
            hall_t[b * HH + ug] = hnew;
            float hi = to_tf32(hnew), lo = to_tf32(hnew - hi);
            int kk8h = ug >> 3, lch = ug & 3, half = (ug >> 2) & 1;
            int wb = b >> 4, rl = b & 15, lrh = rl & 7, rh = rl >> 3;
            int fi = ((kk8h * 4 + wb) * 32 + (lrh * 4 + lch)) * 4 + (rh + half * 2);
            hdst_hi[fi] = hi;
            hdst_lo[fi] = lo;
        }

        // grid barrier (generation-based, self-resetting)
        __threadfence();
        __syncthreads();
        if (tid == 0){
            genbase += 1;
            unsigned arrived = atomicAdd(&g_cnt, 1u);
            if (arrived == NCTA - 1){
                asm volatile("st.volatile.global.u32 [%0], %1;" :: "l"(&g_cnt), "r"(0u));
                __threadfence();
                atomicAdd(&g_gen, 1u);
            } else {
                unsigned cur;
                do {
                    asm volatile("ld.acquire.gpu.global.u32 %0, [%1];" : "=r"(cur) : "l"(&g_gen));
                } while ((int)(cur - genbase) < 0);
            }
        }
        __syncthreads();
    }
}

// ---------------- host launch ----------------
extern "C" void kernel_launch(void* const* d_in, const int* in_sizes, int n_in,
                              void* d_out, int out_size)
{
    const int* x = 0;
    const float *embed = 0, *W_ih = 0, *W_hh = 0, *b_ih = 0, *b_hh = 0, *fc_w = 0, *fc_b = 0;
    for (int i = 0; i < n_in; i++){
        switch (in_sizes[i]){
            case BB*TT:      x     = (const int*)  d_in[i]; break;
            case VV*EE:      embed = (const float*)d_in[i]; break;
            case G4*EE:      W_ih  = (const float*)d_in[i]; break;
            case G4*HH:      W_hh  = (const float*)d_in[i]; break;
            case G4:         if (!b_ih) b_ih = (const float*)d_in[i];
                             else        b_hh = (const float*)d_in[i]; break;
            case VV*HH:      fc_w  = (const float*)d_in[i]; break;
            case VV:         fc_b  = (const float*)d_in[i]; break;
            default: break;  // truncate_length — identity in forward pass
        }
    }
    float* out = (float*)d_out;

    float *p_proj = 0, *p_hall = 0;
    cudaGetSymbolAddress((void**)&p_proj, g_proj);
    cudaGetSymbolAddress((void**)&p_hall, g_hall);

    const int SMEM = 4*WFRAG_F4_PER_CTA*4 + 64*25*4;   // 147456 + 6400
    cudaFuncSetAttribute(k_persist, cudaFuncAttributeMaxDynamicSharedMemorySize, SMEM);

    // 1) prep: fragment-ordered W_hh hi/lo + zero hfrag slot 1 (replay-safe)
    {
        int n = NCTA * WFRAG_F4_PER_CTA;   // 1,179,648
        k_prep<<<(n + 255) / 256, 256>>>(W_hh);
    }
    // 2) proj[V,4H] = embed @ W_ih^T + b_ih + b_hh
    {
        dim3 grid(G4 / 128, (VV + 127) / 128);
        k_gemm<false><<<grid, 256>>>(embed, W_ih, p_proj, VV, G4, EE, b_ih, b_hh);
    }
    // 3) persistent recurrence: 512 steps, 1 launch
    k_persist<<<NCTA, 128, SMEM>>>(x);
    // 4) out[B,T,V] = hall @ fc_w^T + fc_b
    {
        dim3 grid((VV + 127) / 128, (BB * TT) / 128);
        k_gemm<true><<<grid, 256>>>(p_hall, fc_w, out, BB * TT, VV, HH, fc_b, (const float*)0);
    }
}

// round 9
// speedup vs baseline: 2.1548x; 1.6431x over previous
#include <cuda_runtime.h>
#include <cuda_bf16.h>
#include <cstdint>
#include <math.h>

#define BB 64
#define TT 512
#define EE 256
#define HH 768
#define G4 3072
#define VV 5000

#define NCTA 128          // persistent CTAs, 6 hidden units each
#define UPC  6
#define NKC  48           // K=768 / 16 (bf16 mma k16 chunks)
#define WFRAG_U4_PER_CTA (NKC*3*32)     // 4608 uint4 per CTA (weights, bf16 hi/lo packed)
#define HFRAG_E 49152                   // 64*768 bf16 elements per slot

// ---------------- device scratch ----------------
__device__ float g_proj[(size_t)VV * G4];                 // embed@W_ih^T + biases
__device__ __align__(16) uint4 g_wfrag[(size_t)NCTA * WFRAG_U4_PER_CTA]; // W_hh B-fragments
__device__ float g_hall[(size_t)TT * BB * HH];            // h states [t][b][H] fp32 (FC input)
__device__ __align__(16) __nv_bfloat16 g_fh[2][HFRAG_E];  // h bf16-hi, A-fragment order
__device__ __align__(16) __nv_bfloat16 g_fl[2][HFRAG_E];  // h bf16-lo residual
__device__ unsigned g_cnt = 0;                            // barrier arrive count
__device__ unsigned g_gen = 0;                            // barrier generation

__device__ __forceinline__ float to_tf32(float x){
    uint32_t u; asm("cvt.rna.tf32.f32 %0, %1;" : "=r"(u) : "f"(x));
    return __uint_as_float(u);
}
__device__ __forceinline__ uint32_t fu(float x){ return __float_as_uint(x); }

__device__ __forceinline__ void mma_tf32(float* c, const uint32_t* a, const uint32_t* b){
    asm volatile("mma.sync.aligned.m16n8k8.row.col.f32.tf32.tf32.f32 "
        "{%0,%1,%2,%3}, {%4,%5,%6,%7}, {%8,%9}, {%0,%1,%2,%3};"
        : "+f"(c[0]), "+f"(c[1]), "+f"(c[2]), "+f"(c[3])
        : "r"(a[0]), "r"(a[1]), "r"(a[2]), "r"(a[3]), "r"(b[0]), "r"(b[1]));
}
__device__ __forceinline__ void mma_bf16(float* c, const uint32_t* a, const uint32_t* b){
    asm volatile("mma.sync.aligned.m16n8k16.row.col.f32.bf16.bf16.f32 "
        "{%0,%1,%2,%3}, {%4,%5,%6,%7}, {%8,%9}, {%0,%1,%2,%3};"
        : "+f"(c[0]), "+f"(c[1]), "+f"(c[2]), "+f"(c[3])
        : "r"(a[0]), "r"(a[1]), "r"(a[2]), "r"(a[3]), "r"(b[0]), "r"(b[1]));
}

__device__ __forceinline__ unsigned short bfbits(float x){
    return __bfloat16_as_ushort(__float2bfloat16_rn(x));
}
__device__ __forceinline__ uint32_t pack_bf2(float lo_elem, float hi_elem){
    // lower k element in lower 16 bits
    return (uint32_t)bfbits(lo_elem) | ((uint32_t)bfbits(hi_elem) << 16);
}

// ---------------- prep: fragment-ordered bf16 hi/lo W_hh; zero h slot 1 ----------------
// m16n8k16 B fragment: lane lr=lane>>2 (n), lc=lane&3; b0 = B[k=2lc,2lc+1][n], b1 = B[k=2lc+8,2lc+9][n].
// CTA row n_local in [0,24): u = n_local>>2, gate = n_local&3 -> W_hh row = gate*HH + cta*6 + u.
// uint4 at (cta*NKC + kc)*3*32 + nt*32 + lane = {b0_hi, b1_hi, b0_lo, b1_lo} packed bf16x2.
__global__ void k_prep(const float* __restrict__ Whh){
    int i = blockIdx.x * blockDim.x + threadIdx.x;
    if (i < HFRAG_E){
        g_fh[1][i] = __float2bfloat16(0.f);
        g_fl[1][i] = __float2bfloat16(0.f);
    }
    if (i < NCTA * WFRAG_U4_PER_CTA){
        int cta = i / WFRAG_U4_PER_CTA;
        int j   = i % WFRAG_U4_PER_CTA;
        int kc  = j / 96;
        int j2  = j % 96;
        int nt  = j2 >> 5;
        int lane= j2 & 31;
        int lr = lane >> 2, lc = lane & 3;
        int n_local = nt * 8 + lr;
        int u = n_local >> 2, gate = n_local & 3;
        int grow = gate * HH + cta * UPC + u;
        const float* wr = Whh + (size_t)grow * HH + kc * 16;
        float w00 = wr[2*lc],     w01 = wr[2*lc + 1];
        float w10 = wr[2*lc + 8], w11 = wr[2*lc + 9];
        float h00 = __bfloat162float(__float2bfloat16_rn(w00));
        float h01 = __bfloat162float(__float2bfloat16_rn(w01));
        float h10 = __bfloat162float(__float2bfloat16_rn(w10));
        float h11 = __bfloat162float(__float2bfloat16_rn(w11));
        uint4 v;
        v.x = pack_bf2(h00, h01);
        v.y = pack_bf2(h10, h11);
        v.z = pack_bf2(w00 - h00, w01 - h01);
        v.w = pack_bf2(w10 - h10, w11 - h11);
        g_wfrag[i] = v;
    }
}

// ---------------- generic tf32 GEMM: C = A[M,K] @ B[N,K]^T + bias ----------------
template<bool PERM>
__global__ __launch_bounds__(256) void k_gemm(
    const float* __restrict__ A, const float* __restrict__ Bm, float* __restrict__ C,
    int M, int N, int K, const float* __restrict__ bias1, const float* __restrict__ bias2)
{
    __shared__ float As[128][36];
    __shared__ float Bs[128][36];
    const int tid = threadIdx.x;
    const int w = tid >> 5, lane = tid & 31;
    const int lr = lane >> 2, lc = lane & 3;
    const int m0 = blockIdx.y * 128, n0 = blockIdx.x * 128;
    const int wm = (w >> 1) * 32, wn = (w & 1) * 64;

    float acc[2][8][4];
    #pragma unroll
    for (int i = 0; i < 2; i++)
        #pragma unroll
        for (int j = 0; j < 8; j++)
            #pragma unroll
            for (int q = 0; q < 4; q++) acc[i][j][q] = 0.f;

    float4 pa[4], pb[4];
    #pragma unroll
    for (int i = 0; i < 4; i++){
        int f = tid + i * 256; int r = f >> 3, cf = (f & 7) * 4;
        pa[i] = make_float4(0.f,0.f,0.f,0.f);
        if (m0 + r < M) pa[i] = *(const float4*)(A + (size_t)(m0 + r) * K + cf);
        pb[i] = make_float4(0.f,0.f,0.f,0.f);
        if (n0 + r < N) pb[i] = *(const float4*)(Bm + (size_t)(n0 + r) * K + cf);
    }

    for (int k0 = 0; k0 < K; k0 += 32){
        #pragma unroll
        for (int i = 0; i < 4; i++){
            int f = tid + i * 256; int r = f >> 3, cf = (f & 7) * 4;
            float4 ta = pa[i], tb = pb[i];
            As[r][cf+0] = to_tf32(ta.x); As[r][cf+1] = to_tf32(ta.y);
            As[r][cf+2] = to_tf32(ta.z); As[r][cf+3] = to_tf32(ta.w);
            Bs[r][cf+0] = to_tf32(tb.x); Bs[r][cf+1] = to_tf32(tb.y);
            Bs[r][cf+2] = to_tf32(tb.z); Bs[r][cf+3] = to_tf32(tb.w);
        }
        __syncthreads();
        int k1 = k0 + 32;
        if (k1 < K){
            #pragma unroll
            for (int i = 0; i < 4; i++){
                int f = tid + i * 256; int r = f >> 3, cf = (f & 7) * 4;
                pa[i] = make_float4(0.f,0.f,0.f,0.f);
                if (m0 + r < M) pa[i] = *(const float4*)(A + (size_t)(m0 + r) * K + k1 + cf);
                pb[i] = make_float4(0.f,0.f,0.f,0.f);
                if (n0 + r < N) pb[i] = *(const float4*)(Bm + (size_t)(n0 + r) * K + k1 + cf);
            }
        }
        #pragma unroll
        for (int kk = 0; kk < 32; kk += 8){
            uint32_t af[2][4], bf[8][2];
            #pragma unroll
            for (int mt = 0; mt < 2; mt++){
                int rb = wm + mt * 16;
                af[mt][0] = fu(As[rb + lr][kk + lc]);
                af[mt][1] = fu(As[rb + 8 + lr][kk + lc]);
                af[mt][2] = fu(As[rb + lr][kk + lc + 4]);
                af[mt][3] = fu(As[rb + 8 + lr][kk + lc + 4]);
            }
            #pragma unroll
            for (int nt = 0; nt < 8; nt++){
                int cb = wn + nt * 8;
                bf[nt][0] = fu(Bs[cb + lr][kk + lc]);
                bf[nt][1] = fu(Bs[cb + lr][kk + lc + 4]);
            }
            #pragma unroll
            for (int mt = 0; mt < 2; mt++)
                #pragma unroll
                for (int nt = 0; nt < 8; nt++)
                    mma_tf32(acc[mt][nt], af[mt], bf[nt]);
        }
        __syncthreads();
    }

    #pragma unroll
    for (int mt = 0; mt < 2; mt++)
        #pragma unroll
        for (int nt = 0; nt < 8; nt++){
            #pragma unroll
            for (int q = 0; q < 4; q++){
                int row = m0 + wm + mt * 16 + lr + (q >> 1) * 8;
                int col = n0 + wn + nt * 8 + lc * 2 + (q & 1);
                if (row < M && col < N){
                    float v = acc[mt][nt][q];
                    if (bias1) v += bias1[col];
                    if (bias2) v += bias2[col];
                    int orow = row;
                    if (PERM){ int t = row >> 6, b = row & 63; orow = b * TT + t; }
                    C[(size_t)orow * N + col] = v;
                }
            }
        }
}

// ---------------- persistent LSTM recurrence (bf16x3) ----------------
// 128 CTAs x 128 threads. Warp w: batch rows [w*16, w*16+16), all 24 gate cols (3 n8 tiles).
// acc = Ah*Bh + Ah*Bl + Al*Bh with bf16 m16n8k16; fp32 accumulate.
__global__ __launch_bounds__(128, 1) void k_persist(const int* __restrict__ x)
{
    extern __shared__ float sm[];
    uint4* Bsm = (uint4*)sm;                        // 4608 uint4 = 73728 B
    float* gs  = sm + WFRAG_U4_PER_CTA * 4;         // 64 x 25 floats
    const int tid  = threadIdx.x;
    const int w    = tid >> 5, lane = tid & 31;
    const int lr   = lane >> 2, lc2 = (lane & 3) * 2;
    const int cta  = blockIdx.x;

    // persistent weight slice -> smem
    {
        const uint4* wsrc = g_wfrag + (size_t)cta * WFRAG_U4_PER_CTA;
        for (int i = tid; i < WFRAG_U4_PER_CTA; i += 128) Bsm[i] = wsrc[i];
    }

    // epilogue work items: 3 per thread -> (b, u)
    int eb[3], eu[3]; float creg[3];
    const int* xp[3];
    #pragma unroll
    for (int j = 0; j < 3; j++){
        int idx = tid + j * 128;
        eb[j] = idx & 63; eu[j] = idx >> 6;
        creg[j] = 0.f;
        xp[j] = x + eb[j] * TT;
    }
    __syncthreads();

    unsigned genbase = 0;
    if (tid == 0)
        asm volatile("ld.volatile.global.u32 %0, [%1];" : "=r"(genbase) : "l"(&g_gen));

    for (int t = 0; t < TT; t++){
        // prefetch proj gate biases (consumed in epilogue; hidden behind GEMM)
        float pv[3][4];
        #pragma unroll
        for (int j = 0; j < 3; j++){
            int xv = __ldg(xp[j] + t);
            const float* pr = g_proj + (size_t)xv * G4 + (cta * UPC + eu[j]);
            #pragma unroll
            for (int g = 0; g < 4; g++) pv[j][g] = __ldg(pr + g * HH);
        }

        const uint4* Ahi = (const uint4*)g_fh[(t + 1) & 1];  // slot (t-1)&1; t=0 -> zeroed slot 1
        const uint4* Alo = (const uint4*)g_fl[(t + 1) & 1];

        float accHH[3][4], accHL[3][4], accLH[3][4];
        #pragma unroll
        for (int n = 0; n < 3; n++)
            #pragma unroll
            for (int q = 0; q < 4; q++){ accHH[n][q] = 0.f; accHL[n][q] = 0.f; accLH[n][q] = 0.f; }

        // 8-deep A-fragment prefetch ring
        uint4 ahb[8], alb[8];
        #pragma unroll
        for (int j = 0; j < 8; j++){
            int off = (j * 4 + w) * 32 + lane;
            ahb[j] = __ldg(Ahi + off);
            alb[j] = __ldg(Alo + off);
        }
        uint4 bcur[3], bnxt[3];
        #pragma unroll
        for (int nt = 0; nt < 3; nt++) bcur[nt] = Bsm[nt * 32 + lane];

        for (int c = 0; c < 6; c++){
            #pragma unroll
            for (int j = 0; j < 8; j++){
                int kc = c * 8 + j;
                uint4 a4 = ahb[j], l4 = alb[j];
                int kn = kc + 8;
                if (kn < NKC){
                    int off = (kn * 4 + w) * 32 + lane;
                    ahb[j] = __ldg(Ahi + off);
                    alb[j] = __ldg(Alo + off);
                }
                if (kc + 1 < NKC){
                    #pragma unroll
                    for (int nt = 0; nt < 3; nt++)
                        bnxt[nt] = Bsm[((kc + 1) * 3 + nt) * 32 + lane];
                }
                uint32_t ah[4] = {a4.x, a4.y, a4.z, a4.w};
                uint32_t al[4] = {l4.x, l4.y, l4.z, l4.w};
                #pragma unroll
                for (int nt = 0; nt < 3; nt++){
                    uint32_t bh[2] = {bcur[nt].x, bcur[nt].y};
                    uint32_t bl[2] = {bcur[nt].z, bcur[nt].w};
                    mma_bf16(accHH[nt], ah, bh);
                    mma_bf16(accHL[nt], ah, bl);
                    mma_bf16(accLH[nt], al, bh);
                }
                #pragma unroll
                for (int nt = 0; nt < 3; nt++) bcur[nt] = bnxt[nt];
            }
        }

        // gate tile -> smem (C fragment: row = w*16 + lr + (q>>1)*8, col = nt*8 + lc2 + (q&1))
        #pragma unroll
        for (int nt = 0; nt < 3; nt++){
            #pragma unroll
            for (int q = 0; q < 4; q++){
                int row = w * 16 + lr + (q >> 1) * 8;
                int col = nt * 8 + lc2 + (q & 1);
                gs[row * 25 + col] = accHH[nt][q] + accHL[nt][q] + accLH[nt][q];
            }
        }
        __syncthreads();

        // pointwise LSTM + h scatter
        __nv_bfloat16* hdst_hi = g_fh[t & 1];
        __nv_bfloat16* hdst_lo = g_fl[t & 1];
        float* hall_t = g_hall + (size_t)t * (BB * HH);
        #pragma unroll
        for (int j = 0; j < 3; j++){
            int b = eb[j], u = eu[j], ug = cta * UPC + u;
            float gi = gs[b * 25 + 4*u + 0] + pv[j][0];
            float gf = gs[b * 25 + 4*u + 1] + pv[j][1];
            float gg = gs[b * 25 + 4*u + 2] + pv[j][2];
            float go = gs[b * 25 + 4*u + 3] + pv[j][3];
            float si = 1.f / (1.f + expf(-gi));
            float sf = 1.f / (1.f + expf(-gf));
            float so = 1.f / (1.f + expf(-go));
            float cnew = sf * creg[j] + si * tanhf(gg);
            float hnew = so * tanhf(cnew);
            creg[j] = cnew;
            hall_t[b * HH + ug] = hnew;
            // A-fragment scatter: kc = ug>>4, kk = ug&15; r = b&15, wb = b>>4
            int kc = ug >> 4, kk = ug & 15;
            int r = b & 15, wb = b >> 4;
            int lane_h = (r & 7) * 4 + ((kk & 7) >> 1);
            int reg = (r >> 3) + 2 * (kk >> 3);
            int half = kk & 1;
            int elem = (((kc * 4 + wb) * 32 + lane_h) * 4 + reg) * 2 + half;
            __nv_bfloat16 hb = __float2bfloat16_rn(hnew);
            hdst_hi[elem] = hb;
            hdst_lo[elem] = __float2bfloat16_rn(hnew - __bfloat162float(hb));
        }

        // grid barrier (generation-based, self-resetting)
        __threadfence();
        __syncthreads();
        if (tid == 0){
            genbase += 1;
            unsigned arrived = atomicAdd(&g_cnt, 1u);
            if (arrived == NCTA - 1){
                asm volatile("st.volatile.global.u32 [%0], %1;" :: "l"(&g_cnt), "r"(0u));
                __threadfence();
                atomicAdd(&g_gen, 1u);
            } else {
                unsigned cur;
                do {
                    asm volatile("ld.acquire.gpu.global.u32 %0, [%1];" : "=r"(cur) : "l"(&g_gen));
                } while ((int)(cur - genbase) < 0);
            }
        }
        __syncthreads();
    }
}

// ---------------- host launch ----------------
extern "C" void kernel_launch(void* const* d_in, const int* in_sizes, int n_in,
                              void* d_out, int out_size)
{
    const int* x = 0;
    const float *embed = 0, *W_ih = 0, *W_hh = 0, *b_ih = 0, *b_hh = 0, *fc_w = 0, *fc_b = 0;
    for (int i = 0; i < n_in; i++){
        switch (in_sizes[i]){
            case BB*TT:      x     = (const int*)  d_in[i]; break;
            case VV*EE:      embed = (const float*)d_in[i]; break;
            case G4*EE:      W_ih  = (const float*)d_in[i]; break;
            case G4*HH:      W_hh  = (const float*)d_in[i]; break;
            case G4:         if (!b_ih) b_ih = (const float*)d_in[i];
                             else        b_hh = (const float*)d_in[i]; break;
            case VV*HH:      fc_w  = (const float*)d_in[i]; break;
            case VV:         fc_b  = (const float*)d_in[i]; break;
            default: break;  // truncate_length — identity in forward pass
        }
    }
    float* out = (float*)d_out;

    float *p_proj = 0, *p_hall = 0;
    cudaGetSymbolAddress((void**)&p_proj, g_proj);
    cudaGetSymbolAddress((void**)&p_hall, g_hall);

    const int SMEM = WFRAG_U4_PER_CTA * 16 + 64 * 25 * 4;   // 73728 + 6400 = 80128
    cudaFuncSetAttribute(k_persist, cudaFuncAttributeMaxDynamicSharedMemorySize, SMEM);

    // 1) prep: fragment-ordered bf16 W_hh hi/lo + zero h slot 1 (replay-safe)
    {
        int n = NCTA * WFRAG_U4_PER_CTA;   // 589,824
        k_prep<<<(n + 255) / 256, 256>>>(W_hh);
    }
    // 2) proj[V,4H] = embed @ W_ih^T + b_ih + b_hh
    {
        dim3 grid(G4 / 128, (VV + 127) / 128);
        k_gemm<false><<<grid, 256>>>(embed, W_ih, p_proj, VV, G4, EE, b_ih, b_hh);
    }
    // 3) persistent recurrence: 512 steps, 1 launch
    k_persist<<<NCTA, 128, SMEM>>>(x);
    // 4) out[B,T,V] = hall @ fc_w^T + fc_b
    {
        dim3 grid((VV + 127) / 128, (BB * TT) / 128);
        k_gemm<true><<<grid, 256>>>(p_hall, fc_w, out, BB * TT, VV, HH, fc_b, (const float*)0);
    }
}

// round 10
// speedup vs baseline: 2.1731x; 1.0085x over previous
#include <cuda_runtime.h>
#include <cuda_bf16.h>
#include <cstdint>
#include <math.h>

#define BB 64
#define TT 512
#define EE 256
#define HH 768
#define G4 3072
#define VV 5000

#define NCTA 128          // persistent CTAs, 6 hidden units each
#define UPC  6
#define NKC  48           // K=768 / 16 (bf16 mma k16 chunks)
#define NKH  24           // kc chunks per warp half (split-K)
#define WFRAG_U4_PER_CTA (NKC*3*32)     // 4608 uint4 per CTA (weights, bf16 hi/lo packed)
#define HFRAG_E 49152                   // 64*768 bf16 elements per slot

// ---------------- device scratch ----------------
__device__ float g_proj[(size_t)VV * G4];                 // embed@W_ih^T + biases
__device__ __align__(16) uint4 g_wfrag[(size_t)NCTA * WFRAG_U4_PER_CTA]; // W_hh B-fragments
__device__ float g_hall[(size_t)TT * BB * HH];            // h states [t][b][H] fp32 (FC input)
__device__ __align__(16) __nv_bfloat16 g_fh[2][HFRAG_E];  // h bf16-hi, A-fragment order
__device__ __align__(16) __nv_bfloat16 g_fl[2][HFRAG_E];  // h bf16-lo residual
__device__ unsigned g_cnt = 0;                            // barrier arrive count
__device__ unsigned g_gen = 0;                            // barrier generation

__device__ __forceinline__ float to_tf32(float x){
    uint32_t u; asm("cvt.rna.tf32.f32 %0, %1;" : "=r"(u) : "f"(x));
    return __uint_as_float(u);
}
__device__ __forceinline__ uint32_t fu(float x){ return __float_as_uint(x); }

__device__ __forceinline__ void mma_tf32(float* c, const uint32_t* a, const uint32_t* b){
    asm volatile("mma.sync.aligned.m16n8k8.row.col.f32.tf32.tf32.f32 "
        "{%0,%1,%2,%3}, {%4,%5,%6,%7}, {%8,%9}, {%0,%1,%2,%3};"
        : "+f"(c[0]), "+f"(c[1]), "+f"(c[2]), "+f"(c[3])
        : "r"(a[0]), "r"(a[1]), "r"(a[2]), "r"(a[3]), "r"(b[0]), "r"(b[1]));
}
__device__ __forceinline__ void mma_bf16(float* c, const uint32_t* a, const uint32_t* b){
    asm volatile("mma.sync.aligned.m16n8k16.row.col.f32.bf16.bf16.f32 "
        "{%0,%1,%2,%3}, {%4,%5,%6,%7}, {%8,%9}, {%0,%1,%2,%3};"
        : "+f"(c[0]), "+f"(c[1]), "+f"(c[2]), "+f"(c[3])
        : "r"(a[0]), "r"(a[1]), "r"(a[2]), "r"(a[3]), "r"(b[0]), "r"(b[1]));
}

__device__ __forceinline__ unsigned short bfbits(float x){
    return __bfloat16_as_ushort(__float2bfloat16_rn(x));
}
__device__ __forceinline__ uint32_t pack_bf2(float lo_elem, float hi_elem){
    return (uint32_t)bfbits(lo_elem) | ((uint32_t)bfbits(hi_elem) << 16);
}

// ---------------- prep: fragment-ordered bf16 hi/lo W_hh; zero h slot 1 ----------------
// m16n8k16 B fragment: lane lr=lane>>2 (n), lc=lane&3; b0 = B[k=2lc,2lc+1][n], b1 = B[k=2lc+8,2lc+9][n].
// CTA row n_local in [0,24): u = n_local>>2, gate = n_local&3 -> W_hh row = gate*HH + cta*6 + u.
// uint4 at (cta*NKC + kc)*3*32 + nt*32 + lane = {b0_hi, b1_hi, b0_lo, b1_lo} packed bf16x2.
__global__ void k_prep(const float* __restrict__ Whh){
    int i = blockIdx.x * blockDim.x + threadIdx.x;
    if (i < HFRAG_E){
        g_fh[1][i] = __float2bfloat16(0.f);
        g_fl[1][i] = __float2bfloat16(0.f);
    }
    if (i < NCTA * WFRAG_U4_PER_CTA){
        int cta = i / WFRAG_U4_PER_CTA;
        int j   = i % WFRAG_U4_PER_CTA;
        int kc  = j / 96;
        int j2  = j % 96;
        int nt  = j2 >> 5;
        int lane= j2 & 31;
        int lr = lane >> 2, lc = lane & 3;
        int n_local = nt * 8 + lr;
        int u = n_local >> 2, gate = n_local & 3;
        int grow = gate * HH + cta * UPC + u;
        const float* wr = Whh + (size_t)grow * HH + kc * 16;
        float w00 = wr[2*lc],     w01 = wr[2*lc + 1];
        float w10 = wr[2*lc + 8], w11 = wr[2*lc + 9];
        float h00 = __bfloat162float(__float2bfloat16_rn(w00));
        float h01 = __bfloat162float(__float2bfloat16_rn(w01));
        float h10 = __bfloat162float(__float2bfloat16_rn(w10));
        float h11 = __bfloat162float(__float2bfloat16_rn(w11));
        uint4 v;
        v.x = pack_bf2(h00, h01);
        v.y = pack_bf2(h10, h11);
        v.z = pack_bf2(w00 - h00, w01 - h01);
        v.w = pack_bf2(w10 - h10, w11 - h11);
        g_wfrag[i] = v;
    }
}

// ---------------- generic tf32 GEMM: C = A[M,K] @ B[N,K]^T + bias ----------------
template<bool PERM>
__global__ __launch_bounds__(256) void k_gemm(
    const float* __restrict__ A, const float* __restrict__ Bm, float* __restrict__ C,
    int M, int N, int K, const float* __restrict__ bias1, const float* __restrict__ bias2)
{
    __shared__ float As[128][36];
    __shared__ float Bs[128][36];
    const int tid = threadIdx.x;
    const int w = tid >> 5, lane = tid & 31;
    const int lr = lane >> 2, lc = lane & 3;
    const int m0 = blockIdx.y * 128, n0 = blockIdx.x * 128;
    const int wm = (w >> 1) * 32, wn = (w & 1) * 64;

    float acc[2][8][4];
    #pragma unroll
    for (int i = 0; i < 2; i++)
        #pragma unroll
        for (int j = 0; j < 8; j++)
            #pragma unroll
            for (int q = 0; q < 4; q++) acc[i][j][q] = 0.f;

    float4 pa[4], pb[4];
    #pragma unroll
    for (int i = 0; i < 4; i++){
        int f = tid + i * 256; int r = f >> 3, cf = (f & 7) * 4;
        pa[i] = make_float4(0.f,0.f,0.f,0.f);
        if (m0 + r < M) pa[i] = *(const float4*)(A + (size_t)(m0 + r) * K + cf);
        pb[i] = make_float4(0.f,0.f,0.f,0.f);
        if (n0 + r < N) pb[i] = *(const float4*)(Bm + (size_t)(n0 + r) * K + cf);
    }

    for (int k0 = 0; k0 < K; k0 += 32){
        #pragma unroll
        for (int i = 0; i < 4; i++){
            int f = tid + i * 256; int r = f >> 3, cf = (f & 7) * 4;
            float4 ta = pa[i], tb = pb[i];
            As[r][cf+0] = to_tf32(ta.x); As[r][cf+1] = to_tf32(ta.y);
            As[r][cf+2] = to_tf32(ta.z); As[r][cf+3] = to_tf32(ta.w);
            Bs[r][cf+0] = to_tf32(tb.x); Bs[r][cf+1] = to_tf32(tb.y);
            Bs[r][cf+2] = to_tf32(tb.z); Bs[r][cf+3] = to_tf32(tb.w);
        }
        __syncthreads();
        int k1 = k0 + 32;
        if (k1 < K){
            #pragma unroll
            for (int i = 0; i < 4; i++){
                int f = tid + i * 256; int r = f >> 3, cf = (f & 7) * 4;
                pa[i] = make_float4(0.f,0.f,0.f,0.f);
                if (m0 + r < M) pa[i] = *(const float4*)(A + (size_t)(m0 + r) * K + k1 + cf);
                pb[i] = make_float4(0.f,0.f,0.f,0.f);
                if (n0 + r < N) pb[i] = *(const float4*)(Bm + (size_t)(n0 + r) * K + k1 + cf);
            }
        }
        #pragma unroll
        for (int kk = 0; kk < 32; kk += 8){
            uint32_t af[2][4], bf[8][2];
            #pragma unroll
            for (int mt = 0; mt < 2; mt++){
                int rb = wm + mt * 16;
                af[mt][0] = fu(As[rb + lr][kk + lc]);
                af[mt][1] = fu(As[rb + 8 + lr][kk + lc]);
                af[mt][2] = fu(As[rb + lr][kk + lc + 4]);
                af[mt][3] = fu(As[rb + 8 + lr][kk + lc + 4]);
            }
            #pragma unroll
            for (int nt = 0; nt < 8; nt++){
                int cb = wn + nt * 8;
                bf[nt][0] = fu(Bs[cb + lr][kk + lc]);
                bf[nt][1] = fu(Bs[cb + lr][kk + lc + 4]);
            }
            #pragma unroll
            for (int mt = 0; mt < 2; mt++)
                #pragma unroll
                for (int nt = 0; nt < 8; nt++)
                    mma_tf32(acc[mt][nt], af[mt], bf[nt]);
        }
        __syncthreads();
    }

    #pragma unroll
    for (int mt = 0; mt < 2; mt++)
        #pragma unroll
        for (int nt = 0; nt < 8; nt++){
            #pragma unroll
            for (int q = 0; q < 4; q++){
                int row = m0 + wm + mt * 16 + lr + (q >> 1) * 8;
                int col = n0 + wn + nt * 8 + lc * 2 + (q & 1);
                if (row < M && col < N){
                    float v = acc[mt][nt][q];
                    if (bias1) v += bias1[col];
                    if (bias2) v += bias2[col];
                    int orow = row;
                    if (PERM){ int t = row >> 6, b = row & 63; orow = b * TT + t; }
                    C[(size_t)orow * N + col] = v;
                }
            }
        }
}

// ---------------- persistent LSTM recurrence (bf16x3, split-K, 8 warps) ----------------
// 128 CTAs x 256 threads. Warp w: wk = w>>2 selects K half, wm = w&3 selects batch m16 tile.
// Each warp: m16 x n24 (3 n8 tiles) over 24 kc chunks. Partial gates -> 2 smem buffers -> epilogue sum.
__global__ __launch_bounds__(256, 1) void k_persist(const int* __restrict__ x)
{
    extern __shared__ float sm[];
    uint4* Bsm = (uint4*)sm;                        // 4608 uint4 = 73728 B
    float* gs0 = sm + WFRAG_U4_PER_CTA * 4;         // 64 x 25 floats (K-half 0)
    float* gs1 = gs0 + 64 * 25;                     // 64 x 25 floats (K-half 1)
    const int tid  = threadIdx.x;
    const int w    = tid >> 5, lane = tid & 31;
    const int wk   = w >> 2, wm = w & 3;
    const int lr   = lane >> 2, lc2 = (lane & 3) * 2;
    const int cta  = blockIdx.x;
    float* gw = wk ? gs1 : gs0;

    // persistent weight slice -> smem
    {
        const uint4* wsrc = g_wfrag + (size_t)cta * WFRAG_U4_PER_CTA;
        for (int i = tid; i < WFRAG_U4_PER_CTA; i += 256) Bsm[i] = wsrc[i];
    }

    // epilogue work items: up to 2 per thread -> (b, u); 384 items total
    int eb[2], eu[2]; float creg[2]; const int* xp[2]; bool ev[2];
    #pragma unroll
    for (int j = 0; j < 2; j++){
        int idx = tid + j * 256;
        ev[j] = (idx < 384);
        eb[j] = idx & 63; eu[j] = (idx >> 6) & 7;
        creg[j] = 0.f;
        xp[j] = x + eb[j] * TT;
    }
    __syncthreads();

    unsigned genbase = 0;
    if (tid == 0)
        asm volatile("ld.volatile.global.u32 %0, [%1];" : "=r"(genbase) : "l"(&g_gen));

    for (int t = 0; t < TT; t++){
        // prefetch proj gate biases (consumed in epilogue; hidden behind GEMM)
        float pv[2][4];
        #pragma unroll
        for (int j = 0; j < 2; j++){
            if (ev[j]){
                int xv = __ldg(xp[j] + t);
                const float* pr = g_proj + (size_t)xv * G4 + (cta * UPC + eu[j]);
                #pragma unroll
                for (int g = 0; g < 4; g++) pv[j][g] = __ldg(pr + g * HH);
            }
        }

        const uint4* Ahi = (const uint4*)g_fh[(t + 1) & 1];  // slot (t-1)&1; t=0 -> zeroed slot 1
        const uint4* Alo = (const uint4*)g_fl[(t + 1) & 1];

        float accHH[3][4], accHL[3][4], accLH[3][4];
        #pragma unroll
        for (int n = 0; n < 3; n++)
            #pragma unroll
            for (int q = 0; q < 4; q++){ accHH[n][q] = 0.f; accHL[n][q] = 0.f; accLH[n][q] = 0.f; }

        // 6-deep A-fragment prefetch ring over this warp's 24 kc chunks
        uint4 ahb[6], alb[6];
        #pragma unroll
        for (int j = 0; j < 6; j++){
            int kc = wk * NKH + j;
            int off = (kc * 4 + wm) * 32 + lane;
            ahb[j] = __ldg(Ahi + off);
            alb[j] = __ldg(Alo + off);
        }
        uint4 bcur[3], bnxt[3];
        #pragma unroll
        for (int nt = 0; nt < 3; nt++)
            bcur[nt] = Bsm[((wk * NKH) * 3 + nt) * 32 + lane];

        for (int c = 0; c < 4; c++){
            #pragma unroll
            for (int j = 0; j < 6; j++){
                int kl = c * 6 + j;                 // 0..23 within half
                int kc = wk * NKH + kl;
                uint4 a4 = ahb[j], l4 = alb[j];
                int knl = kl + 6;
                if (knl < NKH){
                    int kn = wk * NKH + knl;
                    int off = (kn * 4 + wm) * 32 + lane;
                    ahb[j] = __ldg(Ahi + off);
                    alb[j] = __ldg(Alo + off);
                }
                if (kl + 1 < NKH){
                    #pragma unroll
                    for (int nt = 0; nt < 3; nt++)
                        bnxt[nt] = Bsm[((kc + 1) * 3 + nt) * 32 + lane];
                }
                uint32_t ah[4] = {a4.x, a4.y, a4.z, a4.w};
                uint32_t al[4] = {l4.x, l4.y, l4.z, l4.w};
                #pragma unroll
                for (int nt = 0; nt < 3; nt++){
                    uint32_t bh[2] = {bcur[nt].x, bcur[nt].y};
                    uint32_t bl[2] = {bcur[nt].z, bcur[nt].w};
                    mma_bf16(accHH[nt], ah, bh);
                    mma_bf16(accHL[nt], ah, bl);
                    mma_bf16(accLH[nt], al, bh);
                }
                #pragma unroll
                for (int nt = 0; nt < 3; nt++) bcur[nt] = bnxt[nt];
            }
        }

        // partial gate tile -> this K-half's smem buffer
        #pragma unroll
        for (int nt = 0; nt < 3; nt++){
            #pragma unroll
            for (int q = 0; q < 4; q++){
                int row = wm * 16 + lr + (q >> 1) * 8;
                int col = nt * 8 + lc2 + (q & 1);
                gw[row * 25 + col] = accHH[nt][q] + accHL[nt][q] + accLH[nt][q];
            }
        }
        __syncthreads();

        // pointwise LSTM + h scatter
        __nv_bfloat16* hdst_hi = g_fh[t & 1];
        __nv_bfloat16* hdst_lo = g_fl[t & 1];
        float* hall_t = g_hall + (size_t)t * (BB * HH);
        #pragma unroll
        for (int j = 0; j < 2; j++){
            if (!ev[j]) continue;
            int b = eb[j], u = eu[j], ug = cta * UPC + u;
            float gi = gs0[b * 25 + 4*u + 0] + gs1[b * 25 + 4*u + 0] + pv[j][0];
            float gf = gs0[b * 25 + 4*u + 1] + gs1[b * 25 + 4*u + 1] + pv[j][1];
            float gg = gs0[b * 25 + 4*u + 2] + gs1[b * 25 + 4*u + 2] + pv[j][2];
            float go = gs0[b * 25 + 4*u + 3] + gs1[b * 25 + 4*u + 3] + pv[j][3];
            float si = 1.f / (1.f + expf(-gi));
            float sf = 1.f / (1.f + expf(-gf));
            float so = 1.f / (1.f + expf(-go));
            float cnew = sf * creg[j] + si * tanhf(gg);
            float hnew = so * tanhf(cnew);
            creg[j] = cnew;
            hall_t[b * HH + ug] = hnew;
            // A-fragment scatter: kc = ug>>4, kk = ug&15; r = b&15, wb = b>>4
            int kc = ug >> 4, kk = ug & 15;
            int r = b & 15, wb = b >> 4;
            int lane_h = (r & 7) * 4 + ((kk & 7) >> 1);
            int reg = (r >> 3) + 2 * (kk >> 3);
            int half = kk & 1;
            int elem = (((kc * 4 + wb) * 32 + lane_h) * 4 + reg) * 2 + half;
            __nv_bfloat16 hb = __float2bfloat16_rn(hnew);
            hdst_hi[elem] = hb;
            hdst_lo[elem] = __float2bfloat16_rn(hnew - __bfloat162float(hb));
        }

        // grid barrier (generation-based, self-resetting)
        __threadfence();
        __syncthreads();
        if (tid == 0){
            genbase += 1;
            unsigned arrived = atomicAdd(&g_cnt, 1u);
            if (arrived == NCTA - 1){
                asm volatile("st.volatile.global.u32 [%0], %1;" :: "l"(&g_cnt), "r"(0u));
                __threadfence();
                atomicAdd(&g_gen, 1u);
            } else {
                unsigned cur;
                do {
                    asm volatile("ld.acquire.gpu.global.u32 %0, [%1];" : "=r"(cur) : "l"(&g_gen));
                } while ((int)(cur - genbase) < 0);
            }
        }
        __syncthreads();
    }
}

// ---------------- host launch ----------------
extern "C" void kernel_launch(void* const* d_in, const int* in_sizes, int n_in,
                              void* d_out, int out_size)
{
    const int* x = 0;
    const float *embed = 0, *W_ih = 0, *W_hh = 0, *b_ih = 0, *b_hh = 0, *fc_w = 0, *fc_b = 0;
    for (int i = 0; i < n_in; i++){
        switch (in_sizes[i]){
            case BB*TT:      x     = (const int*)  d_in[i]; break;
            case VV*EE:      embed = (const float*)d_in[i]; break;
            case G4*EE:      W_ih  = (const float*)d_in[i]; break;
            case G4*HH:      W_hh  = (const float*)d_in[i]; break;
            case G4:         if (!b_ih) b_ih = (const float*)d_in[i];
                             else        b_hh = (const float*)d_in[i]; break;
            case VV*HH:      fc_w  = (const float*)d_in[i]; break;
            case VV:         fc_b  = (const float*)d_in[i]; break;
            default: break;  // truncate_length — identity in forward pass
        }
    }
    float* out = (float*)d_out;

    float *p_proj = 0, *p_hall = 0;
    cudaGetSymbolAddress((void**)&p_proj, g_proj);
    cudaGetSymbolAddress((void**)&p_hall, g_hall);

    const int SMEM = WFRAG_U4_PER_CTA * 16 + 2 * 64 * 25 * 4;   // 73728 + 12800 = 86528
    cudaFuncSetAttribute(k_persist, cudaFuncAttributeMaxDynamicSharedMemorySize, SMEM);

    // 1) prep: fragment-ordered bf16 W_hh hi/lo + zero h slot 1 (replay-safe)
    {
        int n = NCTA * WFRAG_U4_PER_CTA;   // 589,824
        k_prep<<<(n + 255) / 256, 256>>>(W_hh);
    }
    // 2) proj[V,4H] = embed @ W_ih^T + b_ih + b_hh
    {
        dim3 grid(G4 / 128, (VV + 127) / 128);
        k_gemm<false><<<grid, 256>>>(embed, W_ih, p_proj, VV, G4, EE, b_ih, b_hh);
    }
    // 3) persistent recurrence: 512 steps, 1 launch
    k_persist<<<NCTA, 256, SMEM>>>(x);
    // 4) out[B,T,V] = hall @ fc_w^T + fc_b
    {
        dim3 grid((VV + 127) / 128, (BB * TT) / 128);
        k_gemm<true><<<grid, 256>>>(p_hall, fc_w, out, BB * TT, VV, HH, fc_b, (const float*)0);
    }
}